// round 7
// baseline (speedup 1.0000x reference)
#include <cuda_runtime.h>
#include <cuda_fp16.h>
#include <math.h>
#include <stdint.h>

#define DIM   768
#define DFF   3072
#define HEADS 12
#define DK    64
#define MAXTOK 8192

// ---------------- device scratch (no allocation allowed) ----------------
__device__ __half g_act [MAXTOK * DIM];
__device__ __half g_ff  [MAXTOK * DFF];
__device__ __half g_qkvh[MAXTOK * 3 * DIM];
__device__ float  g_x1  [MAXTOK * DIM];
__device__ __half g_wq  [3*DIM * DIM];
__device__ __half g_wp  [DIM   * DIM];
__device__ __half g_w1  [DFF   * DIM];
__device__ __half g_w2  [DIM   * DFF];

// ---------------- helpers ----------------
__device__ __forceinline__ uint32_t smem_u32(const void* p){
    uint32_t a;
    asm("{ .reg .u64 t; cvta.to.shared.u64 t, %1; cvt.u32.u64 %0, t; }":"=r"(a):"l"(p));
    return a;
}
#define SWZ(o) ((o) ^ (((o)>>3)&0x70))

__device__ __forceinline__ void cp16(uint32_t d, const void* s){
    asm volatile("cp.async.cg.shared.global [%0], [%1], 16;"::"r"(d),"l"(s):"memory");
}
__device__ __forceinline__ void cp_commit(){ asm volatile("cp.async.commit_group;":::"memory"); }
template<int N> __device__ __forceinline__ void cp_wait(){
    asm volatile("cp.async.wait_group %0;"::"n"(N):"memory");
}
__device__ __forceinline__ uint32_t lds32(uint32_t a){
    uint32_t v; asm volatile("ld.shared.b32 %0, [%1];" : "=r"(v) : "r"(a)); return v;
}
__device__ __forceinline__ void mma16816(float* d, const uint32_t* a, const uint32_t* b){
    asm volatile(
        "mma.sync.aligned.m16n8k16.row.col.f32.f16.f16.f32 "
        "{%0,%1,%2,%3}, {%4,%5,%6,%7}, {%8,%9}, {%0,%1,%2,%3};\n"
        : "+f"(d[0]), "+f"(d[1]), "+f"(d[2]), "+f"(d[3])
        : "r"(a[0]), "r"(a[1]), "r"(a[2]), "r"(a[3]), "r"(b[0]), "r"(b[1]));
}
__device__ __forceinline__ void ldmx4(uint32_t* r, uint32_t addr){
    asm volatile("ldmatrix.sync.aligned.m8n8.x4.shared.b16 {%0,%1,%2,%3}, [%4];"
        : "=r"(r[0]), "=r"(r[1]), "=r"(r[2]), "=r"(r[3]) : "r"(addr));
}
__device__ __forceinline__ void ldmx2t(uint32_t& r0, uint32_t& r1, uint32_t addr){
    asm volatile("ldmatrix.sync.aligned.m8n8.x2.trans.shared.b16 {%0,%1}, [%2];"
        : "=r"(r0), "=r"(r1) : "r"(addr));
}

// ============================================================
// weight repack: fp32 -> fp16, vectorized float4
// ============================================================
__global__ __launch_bounds__(256) void pack_wv(const float4* __restrict__ w,
                                               __half2* __restrict__ o, int total4){
    int i = blockIdx.x * 256 + threadIdx.x;
    if (i < total4){
        float4 v = w[i];
        o[2*i]   = __floats2half2_rn(v.x, v.y);
        o[2*i+1] = __floats2half2_rn(v.z, v.w);
    }
}

// ============================================================
// LayerNorm -> fp16, float4 path, 192 threads (768 = 192*4)
// ============================================================
__global__ __launch_bounds__(192) void ln_pack(
    const float* __restrict__ x, const float* __restrict__ w,
    const float* __restrict__ b, __half* __restrict__ y)
{
    const int t = blockIdx.x, tid = threadIdx.x;
    const float4 v = ((const float4*)(x + (size_t)t * DIM))[tid];
    float s1 = v.x + v.y + v.z + v.w;
    float s2 = v.x*v.x + v.y*v.y + v.z*v.z + v.w*v.w;
#pragma unroll
    for (int off = 16; off; off >>= 1) {
        s1 += __shfl_xor_sync(0xffffffffu, s1, off);
        s2 += __shfl_xor_sync(0xffffffffu, s2, off);
    }
    __shared__ float r1[6], r2[6];
    __shared__ float smu, srstd;
    const int wid = tid >> 5, lane = tid & 31;
    if (lane == 0) { r1[wid] = s1; r2[wid] = s2; }
    __syncthreads();
    if (tid == 0) {
        float a = 0.f, c = 0.f;
#pragma unroll
        for (int i = 0; i < 6; i++) { a += r1[i]; c += r2[i]; }
        const float mu  = a * (1.0f / DIM);
        const float var = c * (1.0f / DIM) - mu * mu;
        smu = mu;
        srstd = rsqrtf(var + 1e-5f);
    }
    __syncthreads();
    const float mu = smu, rstd = srstd;
    const float4 wv = ((const float4*)w)[tid];
    const float4 bv = ((const float4*)b)[tid];
    const float o0 = (v.x - mu) * rstd * wv.x + bv.x;
    const float o1 = (v.y - mu) * rstd * wv.y + bv.y;
    const float o2 = (v.z - mu) * rstd * wv.z + bv.z;
    const float o3 = (v.w - mu) * rstd * wv.w + bv.w;
    __half2* yr = (__half2*)(y + (size_t)t * DIM);
    yr[2*tid]   = __floats2half2_rn(o0, o1);
    yr[2*tid+1] = __floats2half2_rn(o2, o3);
}

// ============================================================
// hgemm2: HMMA GEMM, 128x256x64 block, 8 warps (2m x 4n), warp 64x64.
// ldmatrix.x4 fragment loads. Double-buffered cp.async, SW128 smem.
// EPI 1: +bias+res->fp32 | 2: +bias,GELU->fp16 | 3: +bias->fp16
// ============================================================
#define G2_STAGE 49152                 // A 16KB + B 32KB
#define G2_TOTAL (2*G2_STAGE)

template <int EPI>
__global__ __launch_bounds__(256) void hgemm2(
    const __half* __restrict__ A, const __half* __restrict__ B,
    const float* __restrict__ bias, const float* __restrict__ res,
    float* __restrict__ Co, __half* __restrict__ Cp,
    int N, int K)
{
    extern __shared__ char smem[];
    const uint32_t sb = smem_u32(smem);
    const int tid = threadIdx.x;
    const int wid = tid >> 5, lane = tid & 31;
    const int wm = wid & 1;             // m: 2 x 64
    const int wn = wid >> 1;            // n: 4 x 64
    const int r  = lane >> 2;
    const int c2 = (lane & 3) * 2;
    const int bm = blockIdx.y * 128, bn = blockIdx.x * 256;
    const int NIT = K / 64;

    // ldmatrix.x4 lane addressing (j8 = matrix index group)
    const int j8   = lane >> 3;                    // 0..3
    const int arow = (lane & 7) + ((j8 & 1) << 3); // A: m_local in 16
    const int akb  = (j8 >> 1) << 4;               // A: k-half byte (0/16)
    const int brow = (lane & 7) + ((j8 >> 1) << 3);// B: n_local in 16
    const int bkb  = (j8 & 1) << 4;                // B: k-half byte

    auto load_tile = [&](int it){
        const uint32_t st = sb + (uint32_t)(it & 1) * G2_STAGE;
        const int k0 = it * 64;
        const __half* Ab = A + (size_t)bm * K + k0;
        const __half* Bb = B + (size_t)bn * K + k0;
#pragma unroll
        for (int i = 0; i < 4; i++){
            const int chunk = tid + i * 256;      // 0..1023 (128 rows x 8)
            const int rr = chunk >> 3, cb = (chunk & 7) * 16;
            cp16(st + SWZ((uint32_t)(rr * 128 + cb)),
                 (const char*)(Ab + (size_t)rr * K) + cb);
        }
#pragma unroll
        for (int i = 0; i < 8; i++){
            const int chunk = tid + i * 256;      // 0..2047 (256 rows x 8)
            const int rr = chunk >> 3, cb = (chunk & 7) * 16;
            cp16(st + 16384 + SWZ((uint32_t)(rr * 128 + cb)),
                 (const char*)(Bb + (size_t)rr * K) + cb);
        }
    };

    float acc[4][8][4] = {};

    load_tile(0); cp_commit();
    load_tile(1); cp_commit();

    for (int it = 0; it < NIT; it++){
        cp_wait<1>();
        __syncthreads();
        const uint32_t sA = sb + (uint32_t)(it & 1) * G2_STAGE;
        const uint32_t sB = sA + 16384;
#pragma unroll
        for (int kc = 0; kc < 4; kc++){
            uint32_t a[4][4];
#pragma unroll
            for (int mt = 0; mt < 4; mt++){
                const uint32_t addr = sA + SWZ((uint32_t)(
                    (wm * 64 + mt * 16 + arow) * 128 + kc * 32 + akb));
                ldmx4(a[mt], addr);
            }
            uint32_t b[8][2];
#pragma unroll
            for (int ntp = 0; ntp < 4; ntp++){
                uint32_t rg[4];
                const uint32_t addr = sB + SWZ((uint32_t)(
                    (wn * 64 + ntp * 16 + brow) * 128 + kc * 32 + bkb));
                ldmx4(rg, addr);
                b[2*ntp][0]   = rg[0]; b[2*ntp][1]   = rg[1];
                b[2*ntp+1][0] = rg[2]; b[2*ntp+1][1] = rg[3];
            }
#pragma unroll
            for (int mt = 0; mt < 4; mt++)
#pragma unroll
                for (int nt = 0; nt < 8; nt++)
                    mma16816(acc[mt][nt], a[mt], b[nt]);
        }
        __syncthreads();
        if (it + 2 < NIT) load_tile(it + 2);
        cp_commit();
    }

    // ---- epilogue ----
#pragma unroll
    for (int mt = 0; mt < 4; mt++){
#pragma unroll
        for (int nt = 0; nt < 8; nt++){
            const int row0 = bm + wm * 64 + mt * 16 + r;
            const int col  = bn + wn * 64 + nt * 8 + c2;
            const float b0 = bias[col], b1 = bias[col + 1];
            const float* d = acc[mt][nt];
#pragma unroll
            for (int hh = 0; hh < 2; hh++){
                const int rr = row0 + hh * 8;
                float v0 = d[hh * 2 + 0] + b0;
                float v1 = d[hh * 2 + 1] + b1;
                if (EPI == 1) {
                    const float2 rv = *(const float2*)&res[(size_t)rr * N + col];
                    v0 += rv.x; v1 += rv.y;
                    *(float2*)&Co[(size_t)rr * N + col] = make_float2(v0, v1);
                } else if (EPI == 2) {
                    v0 = 0.5f * v0 * (1.0f + erff(v0 * 0.70710678118654752f));
                    v1 = 0.5f * v1 * (1.0f + erff(v1 * 0.70710678118654752f));
                    *(__half2*)&Cp[(size_t)rr * N + col] = __floats2half2_rn(v0, v1);
                } else {
                    *(__half2*)&Cp[(size_t)rr * N + col] = __floats2half2_rn(v0, v1);
                }
            }
        }
    }
}

// ============================================================
// flash2: HMMA flash attention (proven round 6, unchanged)
// ============================================================
#define FL_SMEM 49152

__global__ __launch_bounds__(256) void flash2(
    const __half* __restrict__ qkv, __half* __restrict__ outp)
{
    extern __shared__ char smc[];
    const uint32_t sb = smem_u32(smc);
    const uint32_t Qs  = sb;
    const uint32_t Ks0 = sb + 16384, Ks1 = sb + 24576;
    const uint32_t Vs0 = sb + 32768, Vs1 = sb + 40960;

    const int tid = threadIdx.x, w = tid >> 5, lane = tid & 31;
    const int r = lane >> 2, c2 = (lane & 3) * 2;
    const int bh = blockIdx.y;
    const int b = bh / HEADS, h = bh % HEADS;
    const int q0 = blockIdx.x * 128;
    const __half* base = qkv + (size_t)b * 1024 * (3 * DIM) + h * DK;

#pragma unroll
    for (int i = 0; i < 4; i++){
        const int chunk = tid + i * 256;
        const int row = chunk >> 3, cb = (chunk & 7) * 16;
        cp16(Qs + SWZ((uint32_t)(row * 128 + cb)),
             (const char*)(base + (size_t)(q0 + row) * (3 * DIM)) + cb);
    }

    auto loadKV = [&](int t){
        const uint32_t sk = (t & 1) ? Ks1 : Ks0;
        const uint32_t sv = (t & 1) ? Vs1 : Vs0;
        const __half* kb = base + DIM     + (size_t)(t * 64) * (3 * DIM);
        const __half* vb = base + 2 * DIM + (size_t)(t * 64) * (3 * DIM);
#pragma unroll
        for (int i = 0; i < 2; i++){
            const int chunk = tid + i * 256;
            const int row = chunk >> 3, cb = (chunk & 7) * 16;
            const uint32_t so = SWZ((uint32_t)(row * 128 + cb));
            cp16(sk + so, (const char*)(kb + (size_t)row * (3 * DIM)) + cb);
            cp16(sv + so, (const char*)(vb + (size_t)row * (3 * DIM)) + cb);
        }
    };

    loadKV(0); cp_commit();
    loadKV(1); cp_commit();

    uint32_t aq[4][4];
    float o[8][4] = {};
    float m0 = -1e30f, m1 = -1e30f, l0 = 0.f, l1 = 0.f;
    const int qrow = w * 16 + r;
    const uint32_t lsel = (uint32_t)(lane & 15);
    const uint32_t vsw  = (uint32_t)((lane & 7) << 4);

    for (int t = 0; t < 16; t++){
        cp_wait<1>();
        __syncthreads();
        if (t == 0){
            const __half2 sc = __half2half2(__float2half(0.125f));
#pragma unroll
            for (int kc = 0; kc < 4; kc++){
                const uint32_t b0 = (uint32_t)(qrow * 128 + (kc * 16 + c2) * 2);
                aq[kc][0] = lds32(Qs + SWZ(b0));
                aq[kc][1] = lds32(Qs + SWZ(b0 + 8 * 128));
                aq[kc][2] = lds32(Qs + SWZ(b0 + 16));
                aq[kc][3] = lds32(Qs + SWZ(b0 + 8 * 128 + 16));
#pragma unroll
                for (int u = 0; u < 4; u++){
                    __half2 hv = *(__half2*)&aq[kc][u];
                    hv = __hmul2(hv, sc);
                    aq[kc][u] = *(uint32_t*)&hv;
                }
            }
        }
        const uint32_t sK = (t & 1) ? Ks1 : Ks0;
        const uint32_t sV = (t & 1) ? Vs1 : Vs0;

        float sf[8][4] = {};
#pragma unroll
        for (int kc = 0; kc < 4; kc++){
#pragma unroll
            for (int j = 0; j < 8; j++){
                uint32_t bb[2];
                const uint32_t b0 = (uint32_t)((j * 8 + r) * 128 + (kc * 16 + c2) * 2);
                bb[0] = lds32(sK + SWZ(b0));
                bb[1] = lds32(sK + SWZ(b0 + 16));
                mma16816(sf[j], aq[kc], bb);
            }
        }

        float mx0 = -1e30f, mx1 = -1e30f;
#pragma unroll
        for (int j = 0; j < 8; j++){
            mx0 = fmaxf(mx0, fmaxf(sf[j][0], sf[j][1]));
            mx1 = fmaxf(mx1, fmaxf(sf[j][2], sf[j][3]));
        }
        mx0 = fmaxf(mx0, __shfl_xor_sync(0xffffffffu, mx0, 1));
        mx0 = fmaxf(mx0, __shfl_xor_sync(0xffffffffu, mx0, 2));
        mx1 = fmaxf(mx1, __shfl_xor_sync(0xffffffffu, mx1, 1));
        mx1 = fmaxf(mx1, __shfl_xor_sync(0xffffffffu, mx1, 2));
        const float mn0 = fmaxf(m0, mx0), mn1 = fmaxf(m1, mx1);
        const float f0 = __expf(m0 - mn0), f1 = __expf(m1 - mn1);
        float s0 = 0.f, s1 = 0.f;
#pragma unroll
        for (int j = 0; j < 8; j++){
            sf[j][0] = __expf(sf[j][0] - mn0);
            sf[j][1] = __expf(sf[j][1] - mn0);
            sf[j][2] = __expf(sf[j][2] - mn1);
            sf[j][3] = __expf(sf[j][3] - mn1);
            s0 += sf[j][0] + sf[j][1];
            s1 += sf[j][2] + sf[j][3];
        }
        s0 += __shfl_xor_sync(0xffffffffu, s0, 1);
        s0 += __shfl_xor_sync(0xffffffffu, s0, 2);
        s1 += __shfl_xor_sync(0xffffffffu, s1, 1);
        s1 += __shfl_xor_sync(0xffffffffu, s1, 2);
        l0 = l0 * f0 + s0;  l1 = l1 * f1 + s1;
        m0 = mn0;           m1 = mn1;
#pragma unroll
        for (int j = 0; j < 8; j++){
            o[j][0] *= f0; o[j][1] *= f0;
            o[j][2] *= f1; o[j][3] *= f1;
        }

        uint32_t pa[4][4];
#pragma unroll
        for (int kc = 0; kc < 4; kc++){
            __half2 h0 = __floats2half2_rn(sf[2*kc][0],   sf[2*kc][1]);
            __half2 h1 = __floats2half2_rn(sf[2*kc][2],   sf[2*kc][3]);
            __half2 h2 = __floats2half2_rn(sf[2*kc+1][0], sf[2*kc+1][1]);
            __half2 h3 = __floats2half2_rn(sf[2*kc+1][2], sf[2*kc+1][3]);
            pa[kc][0] = *(uint32_t*)&h0;
            pa[kc][1] = *(uint32_t*)&h1;
            pa[kc][2] = *(uint32_t*)&h2;
            pa[kc][3] = *(uint32_t*)&h3;
        }

#pragma unroll
        for (int kc = 0; kc < 4; kc++){
#pragma unroll
            for (int j = 0; j < 8; j++){
                uint32_t bb[2];
                const uint32_t addr = sV + (uint32_t)((kc * 16 + lsel) * 128)
                                         + ((uint32_t)(16 * j) ^ vsw);
                ldmx2t(bb[0], bb[1], addr);
                mma16816(o[j], pa[kc], bb);
            }
        }

        __syncthreads();
        if (t + 2 < 16) loadKV(t + 2);
        cp_commit();
    }

    const float inv0 = 1.0f / l0, inv1 = 1.0f / l1;
    __half* p0 = outp + (size_t)(b * 1024 + q0 + qrow) * DIM + h * DK;
    __half* p1 = p0 + 8 * DIM;
#pragma unroll
    for (int j = 0; j < 8; j++){
        *(__half2*)(p0 + j * 8 + c2) = __floats2half2_rn(o[j][0] * inv0, o[j][1] * inv0);
        *(__half2*)(p1 + j * 8 + c2) = __floats2half2_rn(o[j][2] * inv1, o[j][3] * inv1);
    }
}

// ============================================================
// launch
// ============================================================
extern "C" void kernel_launch(void* const* d_in, const int* in_sizes, int n_in,
                              void* d_out, int out_size)
{
    const float* x      = (const float*)d_in[0];
    const float* ln1_w  = (const float*)d_in[1];
    const float* ln1_b  = (const float*)d_in[2];
    const float* qkv_w  = (const float*)d_in[3];
    const float* qkv_b  = (const float*)d_in[4];
    const float* proj_w = (const float*)d_in[5];
    const float* proj_b = (const float*)d_in[6];
    const float* ln2_w  = (const float*)d_in[7];
    const float* ln2_b  = (const float*)d_in[8];
    const float* fc1_w  = (const float*)d_in[9];
    const float* fc1_b  = (const float*)d_in[10];
    const float* fc2_w  = (const float*)d_in[11];
    const float* fc2_b  = (const float*)d_in[12];
    float* out = (float*)d_out;

    const int M = in_sizes[0] / DIM;   // 8192
    const int B = M / 1024;

    __half *act, *ff, *qkvh, *wq, *wp, *w1, *w2;
    float *x1f;
    cudaGetSymbolAddress((void**)&act,  g_act);
    cudaGetSymbolAddress((void**)&ff,   g_ff);
    cudaGetSymbolAddress((void**)&qkvh, g_qkvh);
    cudaGetSymbolAddress((void**)&x1f,  g_x1);
    cudaGetSymbolAddress((void**)&wq,   g_wq);
    cudaGetSymbolAddress((void**)&wp,   g_wp);
    cudaGetSymbolAddress((void**)&w1,   g_w1);
    cudaGetSymbolAddress((void**)&w2,   g_w2);

    cudaFuncSetAttribute((const void*)flash2,
                         cudaFuncAttributeMaxDynamicSharedMemorySize, FL_SMEM);
    cudaFuncSetAttribute((const void*)hgemm2<1>,
                         cudaFuncAttributeMaxDynamicSharedMemorySize, G2_TOTAL);
    cudaFuncSetAttribute((const void*)hgemm2<2>,
                         cudaFuncAttributeMaxDynamicSharedMemorySize, G2_TOTAL);
    cudaFuncSetAttribute((const void*)hgemm2<3>,
                         cudaFuncAttributeMaxDynamicSharedMemorySize, G2_TOTAL);

    pack_wv<<<(3*DIM*DIM/4 + 255)/256, 256>>>((const float4*)qkv_w,  (__half2*)wq, 3*DIM*DIM/4);
    pack_wv<<<(DIM*DIM/4   + 255)/256, 256>>>((const float4*)proj_w, (__half2*)wp, DIM*DIM/4);
    pack_wv<<<(DFF*DIM/4   + 255)/256, 256>>>((const float4*)fc1_w,  (__half2*)w1, DFF*DIM/4);
    pack_wv<<<(DIM*DFF/4   + 255)/256, 256>>>((const float4*)fc2_w,  (__half2*)w2, DIM*DFF/4);

    // 1) ln1 -> fp16 act
    ln_pack<<<M, 192>>>(x, ln1_w, ln1_b, act);
    // 2) qkv = act @ Wqkv^T + b  (fp16 out)
    hgemm2<3><<<dim3((3*DIM)/256, M/128), 256, G2_TOTAL>>>(
        act, wq, qkv_b, nullptr, nullptr, qkvh, 3*DIM, DIM);
    // 3) attention (HMMA) -> fp16 act
    flash2<<<dim3(1024/128, B*HEADS), 256, FL_SMEM>>>(qkvh, act);
    // 4) x1 = x + act @ Wproj^T + b  (fp32 out)
    hgemm2<1><<<dim3(DIM/256, M/128), 256, G2_TOTAL>>>(
        act, wp, proj_b, x, x1f, nullptr, DIM, DIM);
    // 5) ln2 -> fp16 act
    ln_pack<<<M, 192>>>(x1f, ln2_w, ln2_b, act);
    // 6) ff = gelu(act @ Wfc1^T + b)  (fp16 out)
    hgemm2<2><<<dim3(DFF/256, M/128), 256, G2_TOTAL>>>(
        act, w1, fc1_b, nullptr, nullptr, ff, DFF, DIM);
    // 7) out = x1 + ff @ Wfc2^T + b  (fp32 out)
    hgemm2<1><<<dim3(DIM/256, M/128), 256, G2_TOTAL>>>(
        ff, w2, fc2_b, x1f, out, nullptr, DIM, DFF);
}